// round 11
// baseline (speedup 1.0000x reference)
#include <cuda_runtime.h>
#include <cstdint>

#define NQ 32
#define NS 25
#define NL 64
#define NF 256
#define NH 64
#define NT (NQ * NS * 2)     // 1600 (q, s, i-half) tiles
#define XSP 260              // proj xs row stride (pad 4)
#define ATS 36               // attT row stride (floats; mult of 4)

// Scratch (allocation-free rule: __device__ globals)
__device__ float g_WqT[NQ * NH * NL];  // per q: [h][i]
__device__ float g_WhT[NS * NH * NL];  // per s: [h][j]
__device__ unsigned g_ticket;

typedef unsigned long long u64;

__device__ __forceinline__ float fast_ex2(float x) {
    float r; asm("ex2.approx.f32 %0, %1;" : "=f"(r) : "f"(x)); return r;
}
__device__ __forceinline__ float fast_rcp(float x) {
    float r; asm("rcp.approx.f32 %0, %1;" : "=f"(r) : "f"(x)); return r;
}
__device__ __forceinline__ float fast_tanh(float x) {
    float r; asm("tanh.approx.f32 %0, %1;" : "=f"(r) : "f"(x)); return r;
}
__device__ __forceinline__ u64 f2fma(u64 a, u64 b, u64 c) {
    u64 r; asm("fma.rn.f32x2 %0, %1, %2, %3;" : "=l"(r) : "l"(a), "l"(b), "l"(c)); return r;
}
__device__ __forceinline__ u64 dup2(float x) {
    u64 r; asm("mov.b64 %0, {%1, %1};" : "=l"(r) : "f"(x)); return r;
}

#define LOG2E 1.4426950408889634f

// K1: projection (+ ticket reset for persistent k_attn).
// One block per (sequence b, l-quarter).
__global__ __launch_bounds__(256) void k_project(const float* __restrict__ qs,
                                                 const float* __restrict__ hs,
                                                 const float* __restrict__ W,
                                                 const float* __restrict__ bias) {
    __shared__ float xs[16 * XSP];
    const int b  = blockIdx.x >> 2;
    const int lq = blockIdx.x & 3;
    const int t  = threadIdx.x;

    if (blockIdx.x == 0 && t == 0) g_ticket = 0u;  // visible to k_attn (kernel order)

    const float* x = ((b < NQ) ? (qs + (size_t)b * NL * NF)
                               : (hs + (size_t)(b - NQ) * NL * NF))
                     + (size_t)lq * 16 * NF;
    float* dst = (b < NQ) ? (g_WqT + (size_t)b * NH * NL)
                          : (g_WhT + (size_t)(b - NQ) * NH * NL);

    for (int e = t; e < 16 * NF / 4; e += 256) {
        int row = e >> 6;
        int c4 = (e & 63) * 4;
        *reinterpret_cast<float4*>(&xs[row * XSP + c4]) =
            *reinterpret_cast<const float4*>(&x[row * NF + c4]);
    }
    __syncthreads();

    const int h0 = 4 * (t >> 4);   // W loads broadcast across 16 lanes
    const int lr = t & 15;
    float acc[4] = {0.f, 0.f, 0.f, 0.f};

    #pragma unroll 2
    for (int f = 0; f < NF; f += 4) {
        float4 xv = *reinterpret_cast<const float4*>(&xs[lr * XSP + f]);
        #pragma unroll
        for (int c = 0; c < 4; c++) {
            float4 w = __ldg(reinterpret_cast<const float4*>(&W[(size_t)(h0 + c) * NF + f]));
            acc[c] = fmaf(w.x, xv.x, fmaf(w.y, xv.y, fmaf(w.z, xv.z, fmaf(w.w, xv.w, acc[c]))));
        }
    }
    const int l = lq * 16 + lr;
    #pragma unroll
    for (int c = 0; c < 4; c++)
        dst[(h0 + c) * NL + l] = acc[c] + __ldg(&bias[h0 + c]);
}

// K2: persistent fused kernel over 1600 (q, s, i-half) tiles, occ-5 target.
// smem (floats): wqh[0..2048)=[NH][32]; whT[2048..6144)=[NH][64]
//   overlay: attT[0..2304)=[64 j][ATS] plain floats [j][i-local]
//   ticket slot at [6144]. Total 6148 f = 24592 B.
// Phase C reads hs straight from gmem (L1-broadcast across warps, L2-resident
// across same-s tiles) -- no staging, no staging barriers.
__global__ __launch_bounds__(256, 5) void k_attn(const float* __restrict__ hs,
                                                 float* __restrict__ out) {
    extern __shared__ float sm[];
    float* wqh = sm;             // [NH][32]
    float* whT = sm + 2048;      // [NH][64]
    float* attT = sm;            // overlay: [j][i-local], stride ATS
    float* tslot = sm + 6144;

    const int t = threadIdx.x;

    for (;;) {
        if (t == 0) tslot[0] = __uint_as_float(atomicAdd(&g_ticket, 1u));
        __syncthreads();   // also fences prior-tile attT reads vs new wqh writes
        const unsigned T = __float_as_uint(tslot[0]);
        if (T >= NT) return;

        const int q = T / (2 * NS);
        const int sb = T % (2 * NS);
        const int s = sb >> 1;
        const int half = sb & 1;

        {
            const float4* bsrc = reinterpret_cast<const float4*>(g_WhT + (size_t)s * NH * NL);
            float4* w2 = reinterpret_cast<float4*>(whT);
            for (int e = t; e < NH * NL / 4; e += 256) w2[e] = bsrc[e];
            const float* aq = g_WqT + (size_t)q * NH * NL + half * 32;
            for (int e = t; e < NH * 32 / 4; e += 256) {
                int h = e >> 3;
                int ii = (e & 7) * 4;
                *reinterpret_cast<float4*>(&wqh[h * 32 + ii]) =
                    *reinterpret_cast<const float4*>(&aq[h * NL + ii]);
            }
        }
        __syncthreads();

        const int i0a = 2 * (t >> 4);   // local query row in [0,32) (broadcast loads)
        const int j0 = 4 * (t & 15);    // support col in [0,64) (coalesced loads)

        // Phase A: acc[r][c] = sum_h tanh(wq[i0a+r][h] * wh[j0+c][h])
        float acc[2][4];
        #pragma unroll
        for (int r = 0; r < 2; r++)
            #pragma unroll
            for (int c = 0; c < 4; c++) acc[r][c] = 0.f;

        #pragma unroll 4
        for (int h = 0; h < NH; h++) {
            float2 a2 = *reinterpret_cast<const float2*>(&wqh[h * 32 + i0a]);
            float4 b4 = *reinterpret_cast<const float4*>(&whT[h * NL + j0]);
            acc[0][0] += fast_tanh(a2.x * b4.x);
            acc[0][1] += fast_tanh(a2.x * b4.y);
            acc[0][2] += fast_tanh(a2.x * b4.z);
            acc[0][3] += fast_tanh(a2.x * b4.w);
            acc[1][0] += fast_tanh(a2.y * b4.x);
            acc[1][1] += fast_tanh(a2.y * b4.y);
            acc[1][2] += fast_tanh(a2.y * b4.z);
            acc[1][3] += fast_tanh(a2.y * b4.w);
        }

        // Phase B: softmax over j per row (64 j of a row live in one 16-lane group).
        float inv[2];
        #pragma unroll
        for (int r = 0; r < 2; r++) {
            float m = fmaxf(fmaxf(acc[r][0], acc[r][1]), fmaxf(acc[r][2], acc[r][3]));
            #pragma unroll
            for (int d = 1; d < 16; d <<= 1)
                m = fmaxf(m, __shfl_xor_sync(0xffffffffu, m, d));
            float e0 = fast_ex2((acc[r][0] - m) * LOG2E);
            float e1 = fast_ex2((acc[r][1] - m) * LOG2E);
            float e2 = fast_ex2((acc[r][2] - m) * LOG2E);
            float e3 = fast_ex2((acc[r][3] - m) * LOG2E);
            acc[r][0] = e0; acc[r][1] = e1; acc[r][2] = e2; acc[r][3] = e3;
            float ssum = (e0 + e1) + (e2 + e3);
            #pragma unroll
            for (int d = 1; d < 16; d <<= 1)
                ssum += __shfl_xor_sync(0xffffffffu, ssum, d);
            inv[r] = fast_rcp(ssum);
        }

        __syncthreads();  // all phase-A smem reads done before overlay writes

        // Store att transposed: attT[j][i-local].
        #pragma unroll
        for (int c = 0; c < 4; c++) {
            #pragma unroll
            for (int r = 0; r < 2; r++)
                attT[(j0 + c) * ATS + (i0a + r)] = acc[r][c] * inv[r];
        }
        __syncthreads();  // attT visible to all warps

        // Phase C: out[i][f] = sum_j att[i][j] * hs[j][f].
        // Warp w owns local rows [4w, 4w+4); lanes span 128 f; 2 f-half passes.
        // hs read directly from gmem (same 128B lines across warps -> L1 hits).
        const float* hg = hs + (size_t)s * NL * NF;
        float* op = out + (size_t)((q * NS + s) * NL + half * 32) * NF;
        const int w = t >> 5;
        const int ib = 4 * w;            // warp-uniform: att loads broadcast
        const int fb = 4 * (t & 31);     // [0,128)

        #pragma unroll
        for (int p = 0; p < 2; p++) {
            const float* hp = hg + 128 * p + fb;
            u64 o[4][2];
            #pragma unroll
            for (int r = 0; r < 4; r++) { o[r][0] = 0ull; o[r][1] = 0ull; }

            #pragma unroll 4
            for (int j = 0; j < NL; j++) {
                float4 a4 = *reinterpret_cast<const float4*>(&attT[j * ATS + ib]);
                ulonglong2 hv = __ldg(reinterpret_cast<const ulonglong2*>(hp + (size_t)j * NF));
                u64 d0 = dup2(a4.x), d1 = dup2(a4.y), d2 = dup2(a4.z), d3 = dup2(a4.w);
                o[0][0] = f2fma(d0, hv.x, o[0][0]); o[0][1] = f2fma(d0, hv.y, o[0][1]);
                o[1][0] = f2fma(d1, hv.x, o[1][0]); o[1][1] = f2fma(d1, hv.y, o[1][1]);
                o[2][0] = f2fma(d2, hv.x, o[2][0]); o[2][1] = f2fma(d2, hv.y, o[2][1]);
                o[3][0] = f2fma(d3, hv.x, o[3][0]); o[3][1] = f2fma(d3, hv.y, o[3][1]);
            }
            #pragma unroll
            for (int r = 0; r < 4; r++) {
                ulonglong2 v; v.x = o[r][0]; v.y = o[r][1];
                *reinterpret_cast<ulonglong2*>(&op[(size_t)(ib + r) * NF + 128 * p + fb]) = v;
            }
        }
        // loop-top __syncthreads fences attT reads vs next tile's smem writes
    }
}

extern "C" void kernel_launch(void* const* d_in, const int* in_sizes, int n_in,
                              void* d_out, int out_size) {
    const float* qs = (const float*)d_in[0];
    const float* hs = (const float*)d_in[1];
    const float* W  = (const float*)d_in[2];
    const float* b  = (const float*)d_in[3];
    float* out = (float*)d_out;

    const int smem_attn = 6148 * (int)sizeof(float);  // 24592 B -> occ 5 (regs-bound)
    cudaFuncSetAttribute(k_attn, cudaFuncAttributeMaxDynamicSharedMemorySize, smem_attn);

    k_project<<<(NQ + NS) * 4, 256>>>(qs, hs, W, b);
    k_attn<<<148 * 5, 256, smem_attn>>>(hs, out);
}